// round 8
// baseline (speedup 1.0000x reference)
#include <cuda_runtime.h>
#include <cstdint>

#define N_NODES   50000
#define N_EDGES   800000
#define N_FEAT    128
#define N_CLASSES 64

// -------- device scratch (no cudaMalloc allowed) --------
__device__ int   g_is64;                                  // 1 if edge_index is int64
__device__ int   g_src[N_EDGES];
__device__ int   g_dst[N_EDGES];
__device__ int   g_cnt[N_NODES];                          // in-degree (excl. self loop)
__device__ int   g_fill[N_NODES];                         // CSR fill cursor (= rowstart copy)
__device__ int   g_rowstart[N_NODES];                     // CSR row offsets
__device__ float g_dinv[N_NODES];                         // deg^-1/2
__device__ int   g_col[N_EDGES];                          // CSR column (src node)
__device__ __align__(16) float g_y [(size_t)N_NODES * N_CLASSES];  // x @ W^T
__device__ __align__(16) float g_h1[(size_t)N_NODES * N_CLASSES];

// ---------------------------------------------------------------------------
// 0) init: zero counters + set dtype flag
// ---------------------------------------------------------------------------
__global__ void k_init(int n) {
    int i = blockIdx.x * blockDim.x + threadIdx.x;
    if (i < n) g_cnt[i] = 0;
    if (i == 0) g_is64 = 1;
}

// 1) dtype detect: int64 node ids (<2^31, LE) have all-zero odd 32-bit words
__global__ void k_detect(const int* __restrict__ buf, int words) {
    int i = blockIdx.x * blockDim.x + threadIdx.x;
    int idx = 2 * i + 1;
    if (idx < words && buf[idx] != 0) g_is64 = 0;   // benign race: all store 0
}

// 2) unpack src/dst (either dtype), clamp, and histogram dst — one pass
__global__ void k_extract_count(const int* __restrict__ buf, int E, int N) {
    int e = blockIdx.x * blockDim.x + threadIdx.x;
    if (e >= E) return;
    int s, d;
    if (g_is64) { s = buf[2 * e];  d = buf[2 * E + 2 * e]; }
    else        { s = buf[e];      d = buf[E + e]; }
    if ((unsigned)s >= (unsigned)N) s = 0;
    if ((unsigned)d >= (unsigned)N) d = 0;
    g_src[e] = s;
    g_dst[e] = d;
    atomicAdd(&g_cnt[d], 1);
}

// ---------------------------------------------------------------------------
// 3) single-block COALESCED tiled scan (warp shfl) -> rowstart, fill cursor,
//    dinv all in one pass. 1024 threads, tiles of 1024 contiguous elements.
// ---------------------------------------------------------------------------
__global__ void k_scan_dinv(int n) {
    __shared__ int wsum[32];
    __shared__ int s_carry;
    const int tid  = threadIdx.x;
    const int lane = tid & 31;
    const int wid  = tid >> 5;
    if (tid == 0) s_carry = 0;
    __syncthreads();

    for (int base = 0; base < n; base += 1024) {
        int idx = base + tid;
        int v = (idx < n) ? g_cnt[idx] : 0;

        // warp-inclusive scan
        int incl = v;
        #pragma unroll
        for (int o = 1; o < 32; o <<= 1) {
            int t = __shfl_up_sync(0xffffffffu, incl, o);
            if (lane >= o) incl += t;
        }
        if (lane == 31) wsum[wid] = incl;
        __syncthreads();

        // warp0 scans the 32 warp totals -> exclusive warp offsets
        if (wid == 0) {
            int w = wsum[lane];
            int wi = w;
            #pragma unroll
            for (int o = 1; o < 32; o <<= 1) {
                int t = __shfl_up_sync(0xffffffffu, wi, o);
                if (lane >= o) wi += t;
            }
            wsum[lane] = wi - w;
        }
        __syncthreads();

        int carry = s_carry;
        int excl  = carry + wsum[wid] + incl - v;
        if (idx < n) {
            g_rowstart[idx] = excl;
            g_fill[idx]     = excl;                  // cursor copy for k_fill
            g_dinv[idx]     = rsqrtf((float)(v + 1));
        }
        __syncthreads();                             // all reads of s_carry/wsum done
        if (tid == 1023) s_carry = carry + wsum[31] + incl;
    }
}

// 4) fill CSR columns through the cursor (pos is the absolute slot directly)
__global__ void k_fill(int E) {
    int e = blockIdx.x * blockDim.x + threadIdx.x;
    if (e >= E) return;
    int pos = atomicAdd(&g_fill[g_dst[e]], 1);
    g_col[pos] = g_src[e];
}

// ---------------------------------------------------------------------------
// 5) y = x @ W^T  (block per node, 64 threads; W = 32 KB stays L1-hot)
// ---------------------------------------------------------------------------
__global__ void k_lin(const float* __restrict__ x, const float* __restrict__ W, int n) {
    int i = blockIdx.x;
    if (i >= n) return;
    int c = threadIdx.x;
    __shared__ float xs[N_FEAT];

    const float* xr = x + (size_t)i * N_FEAT;
    xs[c]      = xr[c];
    xs[c + 64] = xr[c + 64];
    __syncthreads();

    const float* w = W + (size_t)c * N_FEAT;
    float acc = 0.0f;
    #pragma unroll
    for (int k = 0; k < N_FEAT; k += 4) {
        float4 wv = reinterpret_cast<const float4*>(w)[k >> 2];
        acc = fmaf(xs[k],     wv.x, acc);
        acc = fmaf(xs[k + 1], wv.y, acc);
        acc = fmaf(xs[k + 2], wv.z, acc);
        acc = fmaf(xs[k + 3], wv.w, acc);
    }
    g_y[(size_t)i * N_CLASSES + c] = acc;
}

// ---------------------------------------------------------------------------
// Propagation hop core: warp per node, lane owns one float2 (64 feats).
// CSR gather — no float atomics, deterministic.
// ---------------------------------------------------------------------------
__device__ __forceinline__ float2 hop_accum(const float* __restrict__ yin,
                                            int i, int lane) {
    const float di = g_dinv[i];
    const int   rs = g_rowstart[i];
    const int   re = rs + g_cnt[i];

    float ax = 0.0f, ay = 0.0f;
    int e = rs;
    for (; e + 4 <= re; e += 4) {        // 4 outstanding gather chains
        int j0 = g_col[e],     j1 = g_col[e + 1];
        int j2 = g_col[e + 2], j3 = g_col[e + 3];
        float w0 = g_dinv[j0], w1 = g_dinv[j1];
        float w2 = g_dinv[j2], w3 = g_dinv[j3];
        float2 v0 = reinterpret_cast<const float2*>(yin + (size_t)j0 * N_CLASSES)[lane];
        float2 v1 = reinterpret_cast<const float2*>(yin + (size_t)j1 * N_CLASSES)[lane];
        float2 v2 = reinterpret_cast<const float2*>(yin + (size_t)j2 * N_CLASSES)[lane];
        float2 v3 = reinterpret_cast<const float2*>(yin + (size_t)j3 * N_CLASSES)[lane];
        ax = fmaf(w0, v0.x, ax); ay = fmaf(w0, v0.y, ay);
        ax = fmaf(w1, v1.x, ax); ay = fmaf(w1, v1.y, ay);
        ax = fmaf(w2, v2.x, ax); ay = fmaf(w2, v2.y, ay);
        ax = fmaf(w3, v3.x, ax); ay = fmaf(w3, v3.y, ay);
    }
    for (; e < re; e++) {
        int j = g_col[e];
        float w = g_dinv[j];
        float2 v = reinterpret_cast<const float2*>(yin + (size_t)j * N_CLASSES)[lane];
        ax = fmaf(w, v.x, ax); ay = fmaf(w, v.y, ay);
    }

    float2 self = reinterpret_cast<const float2*>(yin + (size_t)i * N_CLASSES)[lane];
    float2 o;
    o.x = fmaf(di, ax, di * di * self.x);
    o.y = fmaf(di, ay, di * di * self.y);
    return o;
}

// 6) hop 1: y -> h1
__global__ void k_hop1() {
    int warp = (blockIdx.x * blockDim.x + threadIdx.x) >> 5;
    int lane = threadIdx.x & 31;
    if (warp >= N_NODES) return;
    float2 o = hop_accum(g_y, warp, lane);
    reinterpret_cast<float2*>(g_h1 + (size_t)warp * N_CLASSES)[lane] = o;
}

// 7) hop 2 fused with bias + log_softmax: h1 -> out  (saves a full pass)
__global__ void k_hop2_head(const float* __restrict__ b, float* __restrict__ out) {
    int warp = (blockIdx.x * blockDim.x + threadIdx.x) >> 5;
    int lane = threadIdx.x & 31;
    if (warp >= N_NODES) return;

    float2 o  = hop_accum(g_h1, warp, lane);
    float2 bb = reinterpret_cast<const float2*>(b)[lane];
    o.x += bb.x;
    o.y += bb.y;

    // warp-wide log_softmax over 64 values (2 per lane)
    float m = fmaxf(o.x, o.y);
    #pragma unroll
    for (int s = 16; s; s >>= 1) m = fmaxf(m, __shfl_xor_sync(0xffffffffu, m, s));

    float ssum = __expf(o.x - m) + __expf(o.y - m);
    #pragma unroll
    for (int s = 16; s; s >>= 1) ssum += __shfl_xor_sync(0xffffffffu, ssum, s);

    float ls = m + __logf(ssum);
    float2 r;
    r.x = o.x - ls;
    r.y = o.y - ls;
    reinterpret_cast<float2*>(out + (size_t)warp * N_CLASSES)[lane] = r;
}

// ---------------------------------------------------------------------------
// launch (8 kernels)
// ---------------------------------------------------------------------------
extern "C" void kernel_launch(void* const* d_in, const int* in_sizes, int n_in,
                              void* d_out, int out_size) {
    // Input remap by element count (metadata-order defense).
    int ix = 0, ie = 1, iw = 2, ib = 3;
    for (int k = 0; k < n_in && k < 4; k++) {
        if      (in_sizes[k] == N_NODES * N_FEAT)   ix = k;
        else if (in_sizes[k] == 2 * N_EDGES)        ie = k;
        else if (in_sizes[k] == N_CLASSES * N_FEAT) iw = k;
        else if (in_sizes[k] == N_CLASSES)          ib = k;
    }
    const float* x    = (const float*)d_in[ix];
    const int*   ebuf = (const int*)d_in[ie];
    const float* W    = (const float*)d_in[iw];
    const float* b    = (const float*)d_in[ib];
    float* out = (float*)d_out;

    const int N = N_NODES;
    const int E = N_EDGES;
    const int ewords = in_sizes[ie];

    k_init         <<<(N + 255) / 256, 256>>>(N);
    k_detect       <<<(ewords / 2 + 255) / 256, 256>>>(ebuf, ewords);
    k_extract_count<<<(E + 255) / 256, 256>>>(ebuf, E, N);
    k_scan_dinv    <<<1, 1024>>>(N);
    k_fill         <<<(E + 255) / 256, 256>>>(E);

    k_lin<<<N, N_CLASSES>>>(x, W, N);

    const long long hop_threads = (long long)N * 32;
    const int hop_blocks = (int)((hop_threads + 255) / 256);
    k_hop1     <<<hop_blocks, 256>>>();
    k_hop2_head<<<hop_blocks, 256>>>(b, out);
}

// round 9
// speedup vs baseline: 1.7005x; 1.7005x over previous
#include <cuda_runtime.h>
#include <cstdint>

#define N_NODES   50000
#define N_EDGES   800000
#define N_FEAT    128
#define N_CLASSES 64

#define SCAN_BLK  1024
#define SCAN_NB   ((N_NODES + SCAN_BLK - 1) / SCAN_BLK)   // 49

// -------- device scratch (no cudaMalloc allowed) --------
__device__ int   g_is64;                                  // 1 if edge_index is int64
__device__ int   g_src[N_EDGES];
__device__ int   g_dst[N_EDGES];
__device__ int   g_cnt[N_NODES];                          // in-degree (excl. self loop)
__device__ int   g_fill[N_NODES];                         // CSR fill cursor (= rowstart copy)
__device__ int   g_rowstart[N_NODES];                     // CSR row offsets
__device__ float g_dinv[N_NODES];                         // deg^-1/2
__device__ int   g_col[N_EDGES];                          // CSR column (src node)
__device__ int   g_part[SCAN_NB];                         // per-block sums
__device__ int   g_part_excl[SCAN_NB];                    // exclusive-scanned block offsets
__device__ __align__(16) float g_y [(size_t)N_NODES * N_CLASSES];  // x @ W^T
__device__ __align__(16) float g_h1[(size_t)N_NODES * N_CLASSES];

// ---------------------------------------------------------------------------
// 0) init: zero counters + set dtype flag
// ---------------------------------------------------------------------------
__global__ void k_init(int n) {
    int i = blockIdx.x * blockDim.x + threadIdx.x;
    if (i < n) g_cnt[i] = 0;
    if (i == 0) g_is64 = 1;
}

// 1) dtype detect: int64 node ids (<2^31, LE) have all-zero odd 32-bit words
__global__ void k_detect(const int* __restrict__ buf, int words) {
    int i = blockIdx.x * blockDim.x + threadIdx.x;
    int idx = 2 * i + 1;
    if (idx < words && buf[idx] != 0) g_is64 = 0;   // benign race: all store 0
}

// 2) unpack src/dst (either dtype), clamp, and histogram dst — one pass
__global__ void k_extract_count(const int* __restrict__ buf, int E, int N) {
    int e = blockIdx.x * blockDim.x + threadIdx.x;
    if (e >= E) return;
    int s, d;
    if (g_is64) { s = buf[2 * e];  d = buf[2 * E + 2 * e]; }
    else        { s = buf[e];      d = buf[E + e]; }
    if ((unsigned)s >= (unsigned)N) s = 0;
    if ((unsigned)d >= (unsigned)N) d = 0;
    g_src[e] = s;
    g_dst[e] = d;
    atomicAdd(&g_cnt[d], 1);
}

// ---------------------------------------------------------------------------
// 3-phase multi-block exclusive scan of g_cnt (49 blocks in parallel)
// ---------------------------------------------------------------------------
// 3a) per-block sums
__global__ void k_scan_partials(int n) {
    __shared__ int wsum[32];
    int idx  = blockIdx.x * SCAN_BLK + threadIdx.x;
    int lane = threadIdx.x & 31;
    int wid  = threadIdx.x >> 5;
    int v = (idx < n) ? g_cnt[idx] : 0;
    #pragma unroll
    for (int o = 16; o; o >>= 1) v += __shfl_xor_sync(0xffffffffu, v, o);
    if (lane == 0) wsum[wid] = v;
    __syncthreads();
    if (wid == 0) {
        int t = wsum[lane];
        #pragma unroll
        for (int o = 16; o; o >>= 1) t += __shfl_xor_sync(0xffffffffu, t, o);
        if (lane == 0) g_part[blockIdx.x] = t;
    }
}

// 3b) exclusive scan of the 49 block sums (one warp; 2 values per lane)
__global__ void k_scan_tops() {
    int lane = threadIdx.x;                       // 32 threads
    int i0 = 2 * lane, i1 = 2 * lane + 1;
    int a = (i0 < SCAN_NB) ? g_part[i0] : 0;
    int b = (i1 < SCAN_NB) ? g_part[i1] : 0;
    int pair = a + b;
    int incl = pair;
    #pragma unroll
    for (int o = 1; o < 32; o <<= 1) {
        int t = __shfl_up_sync(0xffffffffu, incl, o);
        if (lane >= o) incl += t;
    }
    int excl = incl - pair;                       // exclusive offset of the pair
    if (i0 < SCAN_NB) g_part_excl[i0] = excl;
    if (i1 < SCAN_NB) g_part_excl[i1] = excl + a;
}

// 3c) apply: tile scan + block offset -> rowstart, fill cursor, dinv
__global__ void k_scan_apply(int n) {
    __shared__ int wsum[32];
    int idx  = blockIdx.x * SCAN_BLK + threadIdx.x;
    int lane = threadIdx.x & 31;
    int wid  = threadIdx.x >> 5;
    int v = (idx < n) ? g_cnt[idx] : 0;

    int incl = v;
    #pragma unroll
    for (int o = 1; o < 32; o <<= 1) {
        int t = __shfl_up_sync(0xffffffffu, incl, o);
        if (lane >= o) incl += t;
    }
    if (lane == 31) wsum[wid] = incl;
    __syncthreads();
    if (wid == 0) {
        int w = wsum[lane];
        int wi = w;
        #pragma unroll
        for (int o = 1; o < 32; o <<= 1) {
            int t = __shfl_up_sync(0xffffffffu, wi, o);
            if (lane >= o) wi += t;
        }
        wsum[lane] = wi - w;                      // exclusive warp offset
    }
    __syncthreads();

    if (idx < n) {
        int excl = g_part_excl[blockIdx.x] + wsum[wid] + incl - v;
        g_rowstart[idx] = excl;
        g_fill[idx]     = excl;
        g_dinv[idx]     = rsqrtf((float)(v + 1));
    }
}

// 4) fill CSR columns through the cursor (pos is the absolute slot directly)
__global__ void k_fill(int E) {
    int e = blockIdx.x * blockDim.x + threadIdx.x;
    if (e >= E) return;
    int pos = atomicAdd(&g_fill[g_dst[e]], 1);
    g_col[pos] = g_src[e];
}

// ---------------------------------------------------------------------------
// 5) y = x @ W^T  (block per node, 64 threads; W = 32 KB stays L1-hot)
// ---------------------------------------------------------------------------
__global__ void k_lin(const float* __restrict__ x, const float* __restrict__ W, int n) {
    int i = blockIdx.x;
    if (i >= n) return;
    int c = threadIdx.x;
    __shared__ float xs[N_FEAT];

    const float* xr = x + (size_t)i * N_FEAT;
    xs[c]      = xr[c];
    xs[c + 64] = xr[c + 64];
    __syncthreads();

    const float* w = W + (size_t)c * N_FEAT;
    float acc = 0.0f;
    #pragma unroll
    for (int k = 0; k < N_FEAT; k += 4) {
        float4 wv = reinterpret_cast<const float4*>(w)[k >> 2];
        acc = fmaf(xs[k],     wv.x, acc);
        acc = fmaf(xs[k + 1], wv.y, acc);
        acc = fmaf(xs[k + 2], wv.z, acc);
        acc = fmaf(xs[k + 3], wv.w, acc);
    }
    g_y[(size_t)i * N_CLASSES + c] = acc;
}

// ---------------------------------------------------------------------------
// Propagation hop core: warp per node, lane owns one float2 (64 feats).
// CSR gather — no float atomics, deterministic.
// ---------------------------------------------------------------------------
__device__ __forceinline__ float2 hop_accum(const float* __restrict__ yin,
                                            int i, int lane) {
    const float di = g_dinv[i];
    const int   rs = g_rowstart[i];
    const int   re = rs + g_cnt[i];

    float ax = 0.0f, ay = 0.0f;
    int e = rs;
    for (; e + 4 <= re; e += 4) {        // 4 outstanding gather chains
        int j0 = g_col[e],     j1 = g_col[e + 1];
        int j2 = g_col[e + 2], j3 = g_col[e + 3];
        float w0 = g_dinv[j0], w1 = g_dinv[j1];
        float w2 = g_dinv[j2], w3 = g_dinv[j3];
        float2 v0 = reinterpret_cast<const float2*>(yin + (size_t)j0 * N_CLASSES)[lane];
        float2 v1 = reinterpret_cast<const float2*>(yin + (size_t)j1 * N_CLASSES)[lane];
        float2 v2 = reinterpret_cast<const float2*>(yin + (size_t)j2 * N_CLASSES)[lane];
        float2 v3 = reinterpret_cast<const float2*>(yin + (size_t)j3 * N_CLASSES)[lane];
        ax = fmaf(w0, v0.x, ax); ay = fmaf(w0, v0.y, ay);
        ax = fmaf(w1, v1.x, ax); ay = fmaf(w1, v1.y, ay);
        ax = fmaf(w2, v2.x, ax); ay = fmaf(w2, v2.y, ay);
        ax = fmaf(w3, v3.x, ax); ay = fmaf(w3, v3.y, ay);
    }
    for (; e < re; e++) {
        int j = g_col[e];
        float w = g_dinv[j];
        float2 v = reinterpret_cast<const float2*>(yin + (size_t)j * N_CLASSES)[lane];
        ax = fmaf(w, v.x, ax); ay = fmaf(w, v.y, ay);
    }

    float2 self = reinterpret_cast<const float2*>(yin + (size_t)i * N_CLASSES)[lane];
    float2 o;
    o.x = fmaf(di, ax, di * di * self.x);
    o.y = fmaf(di, ay, di * di * self.y);
    return o;
}

// 6) hop 1: y -> h1
__global__ void k_hop1() {
    int warp = (blockIdx.x * blockDim.x + threadIdx.x) >> 5;
    int lane = threadIdx.x & 31;
    if (warp >= N_NODES) return;
    float2 o = hop_accum(g_y, warp, lane);
    reinterpret_cast<float2*>(g_h1 + (size_t)warp * N_CLASSES)[lane] = o;
}

// 7) hop 2 fused with bias + log_softmax: h1 -> out
__global__ void k_hop2_head(const float* __restrict__ b, float* __restrict__ out) {
    int warp = (blockIdx.x * blockDim.x + threadIdx.x) >> 5;
    int lane = threadIdx.x & 31;
    if (warp >= N_NODES) return;

    float2 o  = hop_accum(g_h1, warp, lane);
    float2 bb = reinterpret_cast<const float2*>(b)[lane];
    o.x += bb.x;
    o.y += bb.y;

    float m = fmaxf(o.x, o.y);
    #pragma unroll
    for (int s = 16; s; s >>= 1) m = fmaxf(m, __shfl_xor_sync(0xffffffffu, m, s));

    float ssum = __expf(o.x - m) + __expf(o.y - m);
    #pragma unroll
    for (int s = 16; s; s >>= 1) ssum += __shfl_xor_sync(0xffffffffu, ssum, s);

    float ls = m + __logf(ssum);
    float2 r;
    r.x = o.x - ls;
    r.y = o.y - ls;
    reinterpret_cast<float2*>(out + (size_t)warp * N_CLASSES)[lane] = r;
}

// ---------------------------------------------------------------------------
// launch (10 kernels, all multi-block except the 1-warp scan of 49 partials)
// ---------------------------------------------------------------------------
extern "C" void kernel_launch(void* const* d_in, const int* in_sizes, int n_in,
                              void* d_out, int out_size) {
    int ix = 0, ie = 1, iw = 2, ib = 3;
    for (int k = 0; k < n_in && k < 4; k++) {
        if      (in_sizes[k] == N_NODES * N_FEAT)   ix = k;
        else if (in_sizes[k] == 2 * N_EDGES)        ie = k;
        else if (in_sizes[k] == N_CLASSES * N_FEAT) iw = k;
        else if (in_sizes[k] == N_CLASSES)          ib = k;
    }
    const float* x    = (const float*)d_in[ix];
    const int*   ebuf = (const int*)d_in[ie];
    const float* W    = (const float*)d_in[iw];
    const float* b    = (const float*)d_in[ib];
    float* out = (float*)d_out;

    const int N = N_NODES;
    const int E = N_EDGES;
    const int ewords = in_sizes[ie];

    k_init         <<<(N + 255) / 256, 256>>>(N);
    k_detect       <<<(ewords / 2 + 255) / 256, 256>>>(ebuf, ewords);
    k_extract_count<<<(E + 255) / 256, 256>>>(ebuf, E, N);

    k_scan_partials<<<SCAN_NB, SCAN_BLK>>>(N);
    k_scan_tops    <<<1, 32>>>();
    k_scan_apply   <<<SCAN_NB, SCAN_BLK>>>(N);

    k_fill         <<<(E + 255) / 256, 256>>>(E);

    k_lin<<<N, N_CLASSES>>>(x, W, N);

    const long long hop_threads = (long long)N * 32;
    const int hop_blocks = (int)((hop_threads + 255) / 256);
    k_hop1     <<<hop_blocks, 256>>>();
    k_hop2_head<<<hop_blocks, 256>>>(b, out);
}

// round 10
// speedup vs baseline: 4.6712x; 2.7469x over previous
#include <cuda_runtime.h>
#include <cstdint>

#define N_NODES   50000
#define N_EDGES   800000
#define N_FEAT    128
#define N_CLASSES 64

#define SCAN_BLK  1024
#define SCAN_NB   ((N_NODES + SCAN_BLK - 1) / SCAN_BLK)   // 49

#define LIN_TM    64                                      // nodes per k_lin block
#define LIN_PAD   129                                     // padded row length (bank-conflict-free)
#define LIN_SMEM  ((LIN_TM + N_CLASSES) * LIN_PAD * 4)    // 66048 B dynamic smem

// -------- device scratch (no cudaMalloc allowed) --------
__device__ int   g_is64;
__device__ int   g_src[N_EDGES];
__device__ int   g_dst[N_EDGES];
__device__ int   g_cnt[N_NODES];
__device__ int   g_fill[N_NODES];
__device__ int   g_rowstart[N_NODES];
__device__ float g_dinv[N_NODES];
__device__ int   g_col[N_EDGES];
__device__ int   g_part[SCAN_NB];
__device__ __align__(16) float g_y [(size_t)N_NODES * N_CLASSES];
__device__ __align__(16) float g_h1[(size_t)N_NODES * N_CLASSES];

// ---------------------------------------------------------------------------
// 0) init: zero counters + set dtype flag
// ---------------------------------------------------------------------------
__global__ void k_init(int n) {
    int i = blockIdx.x * blockDim.x + threadIdx.x;
    if (i < n) g_cnt[i] = 0;
    if (i == 0) g_is64 = 1;
}

// 1) dtype detect: int64 node ids (<2^31, LE) have all-zero odd 32-bit words
__global__ void k_detect(const int* __restrict__ buf, int words) {
    int i = blockIdx.x * blockDim.x + threadIdx.x;
    int idx = 2 * i + 1;
    if (idx < words && buf[idx] != 0) g_is64 = 0;   // benign race: all store 0
}

// 2) unpack src/dst (either dtype), clamp, histogram dst
__global__ void k_extract_count(const int* __restrict__ buf, int E, int N) {
    int e = blockIdx.x * blockDim.x + threadIdx.x;
    if (e >= E) return;
    int s, d;
    if (g_is64) { s = buf[2 * e];  d = buf[2 * E + 2 * e]; }
    else        { s = buf[e];      d = buf[E + e]; }
    if ((unsigned)s >= (unsigned)N) s = 0;
    if ((unsigned)d >= (unsigned)N) d = 0;
    g_src[e] = s;
    g_dst[e] = d;
    atomicAdd(&g_cnt[d], 1);
}

// 3a) per-block sums for the scan
__global__ void k_scan_partials(int n) {
    __shared__ int wsum[32];
    int idx  = blockIdx.x * SCAN_BLK + threadIdx.x;
    int lane = threadIdx.x & 31;
    int wid  = threadIdx.x >> 5;
    int v = (idx < n) ? g_cnt[idx] : 0;
    #pragma unroll
    for (int o = 16; o; o >>= 1) v += __shfl_xor_sync(0xffffffffu, v, o);
    if (lane == 0) wsum[wid] = v;
    __syncthreads();
    if (wid == 0) {
        int t = wsum[lane];
        #pragma unroll
        for (int o = 16; o; o >>= 1) t += __shfl_xor_sync(0xffffffffu, t, o);
        if (lane == 0) g_part[blockIdx.x] = t;
    }
}

// ---------------------------------------------------------------------------
// 4) y = x @ W^T  — tiled GEMM. 256 threads, 64 nodes/block.
//    W and x tiles staged in padded smem (coalesced loads, conflict-free reads).
//    Thread (tx,ty) computes nodes {4ty+i} x classes {tx+16j}: 4x4 register tile.
// ---------------------------------------------------------------------------
__global__ __launch_bounds__(256, 3)
void k_lin(const float* __restrict__ x, const float* __restrict__ W, int n) {
    extern __shared__ float sm[];
    float* ws = sm;                              // [N_CLASSES][LIN_PAD]
    float* xs = sm + N_CLASSES * LIN_PAD;        // [LIN_TM][LIN_PAD]

    const int t     = threadIdx.x;
    const int node0 = blockIdx.x * LIN_TM;

    // stage W: 64 rows x 32 float4, coalesced
    for (int f = t; f < N_CLASSES * 32; f += 256) {
        int row = f >> 5, c4 = (f & 31) << 2;
        float4 v = reinterpret_cast<const float4*>(W + (size_t)row * N_FEAT + c4)[0];
        float* p = ws + row * LIN_PAD + c4;
        p[0] = v.x; p[1] = v.y; p[2] = v.z; p[3] = v.w;
    }
    // stage x tile: 64 rows x 32 float4, coalesced (zero-pad past n)
    for (int f = t; f < LIN_TM * 32; f += 256) {
        int row = f >> 5, c4 = (f & 31) << 2;
        int node = node0 + row;
        float4 v = (node < n)
            ? reinterpret_cast<const float4*>(x + (size_t)node * N_FEAT + c4)[0]
            : make_float4(0.f, 0.f, 0.f, 0.f);
        float* p = xs + row * LIN_PAD + c4;
        p[0] = v.x; p[1] = v.y; p[2] = v.z; p[3] = v.w;
    }
    __syncthreads();

    const int tx = t & 15;        // class group: classes tx + 16j
    const int ty = t >> 4;        // node group:  nodes  4ty + i

    float acc[4][4] = {};
    const float* xr = xs + (4 * ty) * LIN_PAD;
    #pragma unroll 4
    for (int k = 0; k < N_FEAT; k++) {
        float a0 = xr[k];
        float a1 = xr[LIN_PAD + k];
        float a2 = xr[2 * LIN_PAD + k];
        float a3 = xr[3 * LIN_PAD + k];
        float b0 = ws[(tx     ) * LIN_PAD + k];
        float b1 = ws[(tx + 16) * LIN_PAD + k];
        float b2 = ws[(tx + 32) * LIN_PAD + k];
        float b3 = ws[(tx + 48) * LIN_PAD + k];
        acc[0][0] = fmaf(a0, b0, acc[0][0]); acc[0][1] = fmaf(a0, b1, acc[0][1]);
        acc[0][2] = fmaf(a0, b2, acc[0][2]); acc[0][3] = fmaf(a0, b3, acc[0][3]);
        acc[1][0] = fmaf(a1, b0, acc[1][0]); acc[1][1] = fmaf(a1, b1, acc[1][1]);
        acc[1][2] = fmaf(a1, b2, acc[1][2]); acc[1][3] = fmaf(a1, b3, acc[1][3]);
        acc[2][0] = fmaf(a2, b0, acc[2][0]); acc[2][1] = fmaf(a2, b1, acc[2][1]);
        acc[2][2] = fmaf(a2, b2, acc[2][2]); acc[2][3] = fmaf(a2, b3, acc[2][3]);
        acc[3][0] = fmaf(a3, b0, acc[3][0]); acc[3][1] = fmaf(a3, b1, acc[3][1]);
        acc[3][2] = fmaf(a3, b2, acc[3][2]); acc[3][3] = fmaf(a3, b3, acc[3][3]);
    }

    #pragma unroll
    for (int i = 0; i < 4; i++) {
        int node = node0 + 4 * ty + i;
        if (node < n) {
            float* o = g_y + (size_t)node * N_CLASSES + tx;
            o[0]  = acc[i][0];
            o[16] = acc[i][1];
            o[32] = acc[i][2];
            o[48] = acc[i][3];
        }
    }
}

// ---------------------------------------------------------------------------
// 5) scan apply (tops inlined): rowstart, fill cursor, dinv
// ---------------------------------------------------------------------------
__global__ void k_scan_apply(int n) {
    __shared__ int wsum[32];
    __shared__ int sexcl[SCAN_NB];
    const int lane = threadIdx.x & 31;
    const int wid  = threadIdx.x >> 5;

    // warp 0: exclusive scan of the 49 block partials (2 per lane)
    if (wid == 0) {
        int i0 = 2 * lane, i1 = 2 * lane + 1;
        int a = (i0 < SCAN_NB) ? g_part[i0] : 0;
        int b = (i1 < SCAN_NB) ? g_part[i1] : 0;
        int pair = a + b, incl = pair;
        #pragma unroll
        for (int o = 1; o < 32; o <<= 1) {
            int tt = __shfl_up_sync(0xffffffffu, incl, o);
            if (lane >= o) incl += tt;
        }
        int excl = incl - pair;
        if (i0 < SCAN_NB) sexcl[i0] = excl;
        if (i1 < SCAN_NB) sexcl[i1] = excl + a;
    }
    __syncthreads();
    const int block_off = sexcl[blockIdx.x];

    int idx = blockIdx.x * SCAN_BLK + threadIdx.x;
    int v = (idx < n) ? g_cnt[idx] : 0;

    int incl = v;
    #pragma unroll
    for (int o = 1; o < 32; o <<= 1) {
        int t = __shfl_up_sync(0xffffffffu, incl, o);
        if (lane >= o) incl += t;
    }
    if (lane == 31) wsum[wid] = incl;
    __syncthreads();
    if (wid == 0) {
        int w = wsum[lane];
        int wi = w;
        #pragma unroll
        for (int o = 1; o < 32; o <<= 1) {
            int t = __shfl_up_sync(0xffffffffu, wi, o);
            if (lane >= o) wi += t;
        }
        wsum[lane] = wi - w;
    }
    __syncthreads();

    if (idx < n) {
        int excl = block_off + wsum[wid] + incl - v;
        g_rowstart[idx] = excl;
        g_fill[idx]     = excl;
        g_dinv[idx]     = rsqrtf((float)(v + 1));
    }
}

// 6) fill CSR columns
__global__ void k_fill(int E) {
    int e = blockIdx.x * blockDim.x + threadIdx.x;
    if (e >= E) return;
    int pos = atomicAdd(&g_fill[g_dst[e]], 1);
    g_col[pos] = g_src[e];
}

// ---------------------------------------------------------------------------
// Propagation hop core: warp per node, lane owns one float2 (64 feats).
// Unroll x8 for deeper outstanding-load chains (avg degree ~16).
// ---------------------------------------------------------------------------
__device__ __forceinline__ float2 hop_accum(const float* __restrict__ yin,
                                            int i, int lane) {
    const float di = g_dinv[i];
    const int   rs = g_rowstart[i];
    const int   re = rs + g_cnt[i];

    float ax = 0.0f, ay = 0.0f;
    int e = rs;
    for (; e + 8 <= re; e += 8) {
        int   j[8];
        float w[8];
        float2 v[8];
        #pragma unroll
        for (int q = 0; q < 8; q++) j[q] = g_col[e + q];
        #pragma unroll
        for (int q = 0; q < 8; q++) w[q] = g_dinv[j[q]];
        #pragma unroll
        for (int q = 0; q < 8; q++)
            v[q] = reinterpret_cast<const float2*>(yin + (size_t)j[q] * N_CLASSES)[lane];
        #pragma unroll
        for (int q = 0; q < 8; q++) {
            ax = fmaf(w[q], v[q].x, ax);
            ay = fmaf(w[q], v[q].y, ay);
        }
    }
    for (; e < re; e++) {
        int jj = g_col[e];
        float w = g_dinv[jj];
        float2 v = reinterpret_cast<const float2*>(yin + (size_t)jj * N_CLASSES)[lane];
        ax = fmaf(w, v.x, ax); ay = fmaf(w, v.y, ay);
    }

    float2 self = reinterpret_cast<const float2*>(yin + (size_t)i * N_CLASSES)[lane];
    float2 o;
    o.x = fmaf(di, ax, di * di * self.x);
    o.y = fmaf(di, ay, di * di * self.y);
    return o;
}

// 7) hop 1: y -> h1
__global__ void k_hop1() {
    int warp = (blockIdx.x * blockDim.x + threadIdx.x) >> 5;
    int lane = threadIdx.x & 31;
    if (warp >= N_NODES) return;
    float2 o = hop_accum(g_y, warp, lane);
    reinterpret_cast<float2*>(g_h1 + (size_t)warp * N_CLASSES)[lane] = o;
}

// 8) hop 2 fused with bias + log_softmax
__global__ void k_hop2_head(const float* __restrict__ b, float* __restrict__ out) {
    int warp = (blockIdx.x * blockDim.x + threadIdx.x) >> 5;
    int lane = threadIdx.x & 31;
    if (warp >= N_NODES) return;

    float2 o  = hop_accum(g_h1, warp, lane);
    float2 bb = reinterpret_cast<const float2*>(b)[lane];
    o.x += bb.x;
    o.y += bb.y;

    float m = fmaxf(o.x, o.y);
    #pragma unroll
    for (int s = 16; s; s >>= 1) m = fmaxf(m, __shfl_xor_sync(0xffffffffu, m, s));

    float ssum = __expf(o.x - m) + __expf(o.y - m);
    #pragma unroll
    for (int s = 16; s; s >>= 1) ssum += __shfl_xor_sync(0xffffffffu, ssum, s);

    float ls = m + __logf(ssum);
    float2 r;
    r.x = o.x - ls;
    r.y = o.y - ls;
    reinterpret_cast<float2*>(out + (size_t)warp * N_CLASSES)[lane] = r;
}

// ---------------------------------------------------------------------------
// launch (9 kernels; k_lin deliberately 4th so ncu profiles it)
// ---------------------------------------------------------------------------
extern "C" void kernel_launch(void* const* d_in, const int* in_sizes, int n_in,
                              void* d_out, int out_size) {
    int ix = 0, ie = 1, iw = 2, ib = 3;
    for (int k = 0; k < n_in && k < 4; k++) {
        if      (in_sizes[k] == N_NODES * N_FEAT)   ix = k;
        else if (in_sizes[k] == 2 * N_EDGES)        ie = k;
        else if (in_sizes[k] == N_CLASSES * N_FEAT) iw = k;
        else if (in_sizes[k] == N_CLASSES)          ib = k;
    }
    const float* x    = (const float*)d_in[ix];
    const int*   ebuf = (const int*)d_in[ie];
    const float* W    = (const float*)d_in[iw];
    const float* b    = (const float*)d_in[ib];
    float* out = (float*)d_out;

    const int N = N_NODES;
    const int E = N_EDGES;
    const int ewords = in_sizes[ie];

    static int smem_set = 0;
    if (!smem_set) {
        cudaFuncSetAttribute(k_lin, cudaFuncAttributeMaxDynamicSharedMemorySize, LIN_SMEM);
        smem_set = 1;
    }

    k_init         <<<(N + 255) / 256, 256>>>(N);                       // 1
    k_detect       <<<(ewords / 2 + 255) / 256, 256>>>(ebuf, ewords);   // 2
    k_extract_count<<<(E + 255) / 256, 256>>>(ebuf, E, N);              // 3
    k_lin          <<<(N + LIN_TM - 1) / LIN_TM, 256, LIN_SMEM>>>(x, W, N); // 4 (profiled)
    k_scan_partials<<<SCAN_NB, SCAN_BLK>>>(N);                          // 5
    k_scan_apply   <<<SCAN_NB, SCAN_BLK>>>(N);                          // 6
    k_fill         <<<(E + 255) / 256, 256>>>(E);                       // 7

    const long long hop_threads = (long long)N * 32;
    const int hop_blocks = (int)((hop_threads + 255) / 256);
    k_hop1     <<<hop_blocks, 256>>>();                                 // 8
    k_hop2_head<<<hop_blocks, 256>>>(b, out);                           // 9
}

// round 11
// speedup vs baseline: 6.1280x; 1.3119x over previous
#include <cuda_runtime.h>
#include <cstdint>

#define N_NODES   50000
#define N_EDGES   800000
#define N_FEAT    128
#define N_CLASSES 64

#define SCAN_BLK  1024
#define SCAN_NB   ((N_NODES + SCAN_BLK - 1) / SCAN_BLK)   // 49

#define LIN_TM    128                                     // nodes per k_lin block
#define LIN_PAD   132                                     // padded row (16B-aligned, low-conflict)
#define LIN_SMEM  ((LIN_TM + N_CLASSES) * LIN_PAD * 4)    // 101376 B dynamic smem

// -------- device scratch (no cudaMalloc allowed) --------
__device__ int   g_is64;
__device__ int   g_src[N_EDGES];
__device__ int   g_dst[N_EDGES];
__device__ int   g_cnt[N_NODES];
__device__ int   g_fill[N_NODES];
__device__ int   g_rowstart[N_NODES];
__device__ float g_dinv[N_NODES];
__device__ int   g_col[N_EDGES];
__device__ int   g_part[SCAN_NB];
__device__ __align__(16) float g_y [(size_t)N_NODES * N_CLASSES];
__device__ __align__(16) float g_h1[(size_t)N_NODES * N_CLASSES];

// ---------------------------------------------------------------------------
// 0) init
// ---------------------------------------------------------------------------
__global__ void k_init(int n) {
    int i = blockIdx.x * blockDim.x + threadIdx.x;
    if (i < n) g_cnt[i] = 0;
    if (i == 0) g_is64 = 1;
}

// 1) dtype detect
__global__ void k_detect(const int* __restrict__ buf, int words) {
    int i = blockIdx.x * blockDim.x + threadIdx.x;
    int idx = 2 * i + 1;
    if (idx < words && buf[idx] != 0) g_is64 = 0;   // benign race: all store 0
}

// 2) unpack + clamp + histogram
__global__ void k_extract_count(const int* __restrict__ buf, int E, int N) {
    int e = blockIdx.x * blockDim.x + threadIdx.x;
    if (e >= E) return;
    int s, d;
    if (g_is64) { s = buf[2 * e];  d = buf[2 * E + 2 * e]; }
    else        { s = buf[e];      d = buf[E + e]; }
    if ((unsigned)s >= (unsigned)N) s = 0;
    if ((unsigned)d >= (unsigned)N) d = 0;
    g_src[e] = s;
    g_dst[e] = d;
    atomicAdd(&g_cnt[d], 1);
}

// ---------------------------------------------------------------------------
// 3) y = x @ W^T — tiled GEMM v2.
//    256 threads, 128 nodes/block. Register tile: 8 nodes x 4 classes.
//    float4 over k: per 4-k chunk 12 LDS.128 + 128 FMA (LDS share ~9%).
// ---------------------------------------------------------------------------
__global__ __launch_bounds__(256, 2)
void k_lin(const float* __restrict__ x, const float* __restrict__ W, int n) {
    extern __shared__ float sm[];
    float* ws = sm;                              // [N_CLASSES][LIN_PAD]
    float* xs = sm + N_CLASSES * LIN_PAD;        // [LIN_TM][LIN_PAD]

    const int t     = threadIdx.x;
    const int node0 = blockIdx.x * LIN_TM;

    // stage W: 64 rows x 32 float4, coalesced
    for (int f = t; f < N_CLASSES * 32; f += 256) {
        int row = f >> 5, c4 = (f & 31) << 2;
        float4 v = reinterpret_cast<const float4*>(W + (size_t)row * N_FEAT + c4)[0];
        reinterpret_cast<float4*>(ws + row * LIN_PAD + c4)[0] = v;
    }
    // stage x tile: 128 rows x 32 float4, coalesced (zero-pad past n)
    for (int f = t; f < LIN_TM * 32; f += 256) {
        int row = f >> 5, c4 = (f & 31) << 2;
        int node = node0 + row;
        float4 v = (node < n)
            ? reinterpret_cast<const float4*>(x + (size_t)node * N_FEAT + c4)[0]
            : make_float4(0.f, 0.f, 0.f, 0.f);
        reinterpret_cast<float4*>(xs + row * LIN_PAD + c4)[0] = v;
    }
    __syncthreads();

    const int tx = t & 15;        // classes tx + 16j (j=0..3)
    const int ty = t >> 4;        // nodes 8*ty + i (i=0..7)

    float acc[8][4] = {};
    const float* xb = xs + (8 * ty) * LIN_PAD;

    for (int k4 = 0; k4 < N_FEAT / 4; k4++) {
        float4 b[4];
        #pragma unroll
        for (int j = 0; j < 4; j++)
            b[j] = reinterpret_cast<const float4*>(ws + (tx + 16 * j) * LIN_PAD)[k4];
        #pragma unroll
        for (int i = 0; i < 8; i++) {
            float4 a = reinterpret_cast<const float4*>(xb + i * LIN_PAD)[k4];
            #pragma unroll
            for (int j = 0; j < 4; j++) {
                acc[i][j] = fmaf(a.x, b[j].x, acc[i][j]);
                acc[i][j] = fmaf(a.y, b[j].y, acc[i][j]);
                acc[i][j] = fmaf(a.z, b[j].z, acc[i][j]);
                acc[i][j] = fmaf(a.w, b[j].w, acc[i][j]);
            }
        }
    }

    #pragma unroll
    for (int i = 0; i < 8; i++) {
        int node = node0 + 8 * ty + i;
        if (node < n) {
            float* o = g_y + (size_t)node * N_CLASSES + tx;
            o[0]  = acc[i][0];
            o[16] = acc[i][1];
            o[32] = acc[i][2];
            o[48] = acc[i][3];
        }
    }
}

// 4) per-block sums for the scan
__global__ void k_scan_partials(int n) {
    __shared__ int wsum[32];
    int idx  = blockIdx.x * SCAN_BLK + threadIdx.x;
    int lane = threadIdx.x & 31;
    int wid  = threadIdx.x >> 5;
    int v = (idx < n) ? g_cnt[idx] : 0;
    #pragma unroll
    for (int o = 16; o; o >>= 1) v += __shfl_xor_sync(0xffffffffu, v, o);
    if (lane == 0) wsum[wid] = v;
    __syncthreads();
    if (wid == 0) {
        int t = wsum[lane];
        #pragma unroll
        for (int o = 16; o; o >>= 1) t += __shfl_xor_sync(0xffffffffu, t, o);
        if (lane == 0) g_part[blockIdx.x] = t;
    }
}

// 5) scan apply (tops inlined): rowstart, fill cursor, dinv
__global__ void k_scan_apply(int n) {
    __shared__ int wsum[32];
    __shared__ int sexcl[SCAN_NB];
    const int lane = threadIdx.x & 31;
    const int wid  = threadIdx.x >> 5;

    if (wid == 0) {
        int i0 = 2 * lane, i1 = 2 * lane + 1;
        int a = (i0 < SCAN_NB) ? g_part[i0] : 0;
        int b = (i1 < SCAN_NB) ? g_part[i1] : 0;
        int pair = a + b, incl = pair;
        #pragma unroll
        for (int o = 1; o < 32; o <<= 1) {
            int tt = __shfl_up_sync(0xffffffffu, incl, o);
            if (lane >= o) incl += tt;
        }
        int excl = incl - pair;
        if (i0 < SCAN_NB) sexcl[i0] = excl;
        if (i1 < SCAN_NB) sexcl[i1] = excl + a;
    }
    __syncthreads();
    const int block_off = sexcl[blockIdx.x];

    int idx = blockIdx.x * SCAN_BLK + threadIdx.x;
    int v = (idx < n) ? g_cnt[idx] : 0;

    int incl = v;
    #pragma unroll
    for (int o = 1; o < 32; o <<= 1) {
        int t = __shfl_up_sync(0xffffffffu, incl, o);
        if (lane >= o) incl += t;
    }
    if (lane == 31) wsum[wid] = incl;
    __syncthreads();
    if (wid == 0) {
        int w = wsum[lane];
        int wi = w;
        #pragma unroll
        for (int o = 1; o < 32; o <<= 1) {
            int t = __shfl_up_sync(0xffffffffu, wi, o);
            if (lane >= o) wi += t;
        }
        wsum[lane] = wi - w;
    }
    __syncthreads();

    if (idx < n) {
        int excl = block_off + wsum[wid] + incl - v;
        g_rowstart[idx] = excl;
        g_fill[idx]     = excl;
        g_dinv[idx]     = rsqrtf((float)(v + 1));
    }
}

// 6) fill CSR columns
__global__ void k_fill(int E) {
    int e = blockIdx.x * blockDim.x + threadIdx.x;
    if (e >= E) return;
    int pos = atomicAdd(&g_fill[g_dst[e]], 1);
    g_col[pos] = g_src[e];
}

// ---------------------------------------------------------------------------
// Hop core: warp per node, lane owns one float2 (64 feats), unroll x8.
// ---------------------------------------------------------------------------
__device__ __forceinline__ float2 hop_accum(const float* __restrict__ yin,
                                            int i, int lane) {
    const float di = g_dinv[i];
    const int   rs = g_rowstart[i];
    const int   re = rs + g_cnt[i];

    float ax = 0.0f, ay = 0.0f;
    int e = rs;
    for (; e + 8 <= re; e += 8) {
        int   j[8];
        float w[8];
        float2 v[8];
        #pragma unroll
        for (int q = 0; q < 8; q++) j[q] = g_col[e + q];
        #pragma unroll
        for (int q = 0; q < 8; q++) w[q] = g_dinv[j[q]];
        #pragma unroll
        for (int q = 0; q < 8; q++)
            v[q] = reinterpret_cast<const float2*>(yin + (size_t)j[q] * N_CLASSES)[lane];
        #pragma unroll
        for (int q = 0; q < 8; q++) {
            ax = fmaf(w[q], v[q].x, ax);
            ay = fmaf(w[q], v[q].y, ay);
        }
    }
    for (; e < re; e++) {
        int jj = g_col[e];
        float w = g_dinv[jj];
        float2 v = reinterpret_cast<const float2*>(yin + (size_t)jj * N_CLASSES)[lane];
        ax = fmaf(w, v.x, ax); ay = fmaf(w, v.y, ay);
    }

    float2 self = reinterpret_cast<const float2*>(yin + (size_t)i * N_CLASSES)[lane];
    float2 o;
    o.x = fmaf(di, ax, di * di * self.x);
    o.y = fmaf(di, ay, di * di * self.y);
    return o;
}

// 7) hop 1: y -> h1
__global__ void k_hop1() {
    int warp = (blockIdx.x * blockDim.x + threadIdx.x) >> 5;
    int lane = threadIdx.x & 31;
    if (warp >= N_NODES) return;
    float2 o = hop_accum(g_y, warp, lane);
    reinterpret_cast<float2*>(g_h1 + (size_t)warp * N_CLASSES)[lane] = o;
}

// 8) hop 2 fused with bias + log_softmax
__global__ void k_hop2_head(const float* __restrict__ b, float* __restrict__ out) {
    int warp = (blockIdx.x * blockDim.x + threadIdx.x) >> 5;
    int lane = threadIdx.x & 31;
    if (warp >= N_NODES) return;

    float2 o  = hop_accum(g_h1, warp, lane);
    float2 bb = reinterpret_cast<const float2*>(b)[lane];
    o.x += bb.x;
    o.y += bb.y;

    float m = fmaxf(o.x, o.y);
    #pragma unroll
    for (int s = 16; s; s >>= 1) m = fmaxf(m, __shfl_xor_sync(0xffffffffu, m, s));

    float ssum = __expf(o.x - m) + __expf(o.y - m);
    #pragma unroll
    for (int s = 16; s; s >>= 1) ssum += __shfl_xor_sync(0xffffffffu, ssum, s);

    float ls = m + __logf(ssum);
    float2 r;
    r.x = o.x - ls;
    r.y = o.y - ls;
    reinterpret_cast<float2*>(out + (size_t)warp * N_CLASSES)[lane] = r;
}

// ---------------------------------------------------------------------------
// launch (9 kernels; k_lin 4th so ncu profiles it)
// ---------------------------------------------------------------------------
extern "C" void kernel_launch(void* const* d_in, const int* in_sizes, int n_in,
                              void* d_out, int out_size) {
    int ix = 0, ie = 1, iw = 2, ib = 3;
    for (int k = 0; k < n_in && k < 4; k++) {
        if      (in_sizes[k] == N_NODES * N_FEAT)   ix = k;
        else if (in_sizes[k] == 2 * N_EDGES)        ie = k;
        else if (in_sizes[k] == N_CLASSES * N_FEAT) iw = k;
        else if (in_sizes[k] == N_CLASSES)          ib = k;
    }
    const float* x    = (const float*)d_in[ix];
    const int*   ebuf = (const int*)d_in[ie];
    const float* W    = (const float*)d_in[iw];
    const float* b    = (const float*)d_in[ib];
    float* out = (float*)d_out;

    const int N = N_NODES;
    const int E = N_EDGES;
    const int ewords = in_sizes[ie];

    static int smem_set = 0;
    if (!smem_set) {
        cudaFuncSetAttribute(k_lin, cudaFuncAttributeMaxDynamicSharedMemorySize, LIN_SMEM);
        smem_set = 1;
    }

    k_init         <<<(N + 255) / 256, 256>>>(N);                       // 1
    k_detect       <<<(ewords / 2 + 255) / 256, 256>>>(ebuf, ewords);   // 2
    k_extract_count<<<(E + 255) / 256, 256>>>(ebuf, E, N);              // 3
    k_lin          <<<(N + LIN_TM - 1) / LIN_TM, 256, LIN_SMEM>>>(x, W, N); // 4 (profiled)
    k_scan_partials<<<SCAN_NB, SCAN_BLK>>>(N);                          // 5
    k_scan_apply   <<<SCAN_NB, SCAN_BLK>>>(N);                          // 6
    k_fill         <<<(E + 255) / 256, 256>>>(E);                       // 7

    const long long hop_threads = (long long)N * 32;
    const int hop_blocks = (int)((hop_threads + 255) / 256);
    k_hop1     <<<hop_blocks, 256>>>();                                 // 8
    k_hop2_head<<<hop_blocks, 256>>>(b, out);                           // 9
}

// round 12
// speedup vs baseline: 7.3025x; 1.1917x over previous
#include <cuda_runtime.h>
#include <cstdint>

#define N_NODES   50000
#define N_EDGES   800000
#define N_FEAT    128
#define N_CLASSES 64

#define SCAN_BLK  1024
#define SCAN_NB   ((N_NODES + SCAN_BLK - 1) / SCAN_BLK)   // 49

#define LIN_TM    128                                     // nodes per k_lin block
#define LIN_KC    64                                      // k-chunk width
#define LIN_PADC  68                                      // padded chunk row (floats)
#define LIN_SMEM  ((LIN_TM + N_CLASSES) * LIN_PADC * 4)   // 52224 B dynamic smem

// -------- device scratch (no cudaMalloc allowed) --------
__device__ int   g_is64;
__device__ int   g_cnt[N_NODES];
__device__ int   g_fill[N_NODES];
__device__ int   g_rowstart[N_NODES];
__device__ float g_dinv[N_NODES];
__device__ int   g_col[N_EDGES];
__device__ int   g_part[SCAN_NB];
__device__ __align__(16) float g_y [(size_t)N_NODES * N_CLASSES];
__device__ __align__(16) float g_h1[(size_t)N_NODES * N_CLASSES];

// ---------------------------------------------------------------------------
// 1) init: zero counters; warp 0 of block 0 detects edge dtype via ballot.
//    int64 node ids (<2^31, LE) have all-zero odd 32-bit words.
// ---------------------------------------------------------------------------
__global__ void k_init(const int* __restrict__ ebuf, int n) {
    int i = blockIdx.x * blockDim.x + threadIdx.x;
    if (i < n) g_cnt[i] = 0;
    if (blockIdx.x == 0 && threadIdx.x < 32) {
        int nz = (ebuf[2 * threadIdx.x + 1] != 0) ? 1 : 0;
        unsigned ball = __ballot_sync(0xffffffffu, nz);
        if (threadIdx.x == 0) g_is64 = (ball == 0) ? 1 : 0;
    }
}

// 2) histogram of dst, decoding raw buffer directly
__global__ void k_count(const int* __restrict__ buf, int E, int N) {
    int e = blockIdx.x * blockDim.x + threadIdx.x;
    if (e >= E) return;
    int d = g_is64 ? buf[2 * E + 2 * e] : buf[E + e];
    if ((unsigned)d >= (unsigned)N) d = 0;
    atomicAdd(&g_cnt[d], 1);
}

// 3) per-block sums for the scan
__global__ void k_scan_partials(int n) {
    __shared__ int wsum[32];
    int idx  = blockIdx.x * SCAN_BLK + threadIdx.x;
    int lane = threadIdx.x & 31;
    int wid  = threadIdx.x >> 5;
    int v = (idx < n) ? g_cnt[idx] : 0;
    #pragma unroll
    for (int o = 16; o; o >>= 1) v += __shfl_xor_sync(0xffffffffu, v, o);
    if (lane == 0) wsum[wid] = v;
    __syncthreads();
    if (wid == 0) {
        int t = wsum[lane];
        #pragma unroll
        for (int o = 16; o; o >>= 1) t += __shfl_xor_sync(0xffffffffu, t, o);
        if (lane == 0) g_part[blockIdx.x] = t;
    }
}

// ---------------------------------------------------------------------------
// 4) y = x @ W^T — tiled GEMM v3: two 64-wide k-chunks, 51 KB smem,
//    3 blocks/SM (24 warps), single wave at grid=391.
//    Register tile 8 nodes x 4 classes, float4 over k.
// ---------------------------------------------------------------------------
__global__ __launch_bounds__(256, 3)
void k_lin(const float* __restrict__ x, const float* __restrict__ W, int n) {
    extern __shared__ float sm[];
    float* ws = sm;                               // [N_CLASSES][LIN_PADC]
    float* xs = sm + N_CLASSES * LIN_PADC;        // [LIN_TM][LIN_PADC]

    const int t     = threadIdx.x;
    const int node0 = blockIdx.x * LIN_TM;
    const int tx    = t & 15;                     // classes tx + 16j
    const int ty    = t >> 4;                     // nodes 8*ty + i

    float acc[8][4] = {};

    #pragma unroll
    for (int c = 0; c < N_FEAT / LIN_KC; c++) {
        const int k0 = c * LIN_KC;

        // stage W chunk: 64 rows x 16 float4, coalesced
        for (int f = t; f < N_CLASSES * 16; f += 256) {
            int row = f >> 4, c4 = (f & 15) << 2;
            float4 v = reinterpret_cast<const float4*>(W + (size_t)row * N_FEAT + k0 + c4)[0];
            reinterpret_cast<float4*>(ws + row * LIN_PADC + c4)[0] = v;
        }
        // stage x chunk: 128 rows x 16 float4, coalesced (zero-pad past n)
        for (int f = t; f < LIN_TM * 16; f += 256) {
            int row = f >> 4, c4 = (f & 15) << 2;
            int node = node0 + row;
            float4 v = (node < n)
                ? reinterpret_cast<const float4*>(x + (size_t)node * N_FEAT + k0 + c4)[0]
                : make_float4(0.f, 0.f, 0.f, 0.f);
            reinterpret_cast<float4*>(xs + row * LIN_PADC + c4)[0] = v;
        }
        __syncthreads();

        const float* xb = xs + (8 * ty) * LIN_PADC;
        #pragma unroll
        for (int k4 = 0; k4 < LIN_KC / 4; k4++) {
            float4 b[4];
            #pragma unroll
            for (int j = 0; j < 4; j++)
                b[j] = reinterpret_cast<const float4*>(ws + (tx + 16 * j) * LIN_PADC)[k4];
            #pragma unroll
            for (int i = 0; i < 8; i++) {
                float4 a = reinterpret_cast<const float4*>(xb + i * LIN_PADC)[k4];
                #pragma unroll
                for (int j = 0; j < 4; j++) {
                    acc[i][j] = fmaf(a.x, b[j].x, acc[i][j]);
                    acc[i][j] = fmaf(a.y, b[j].y, acc[i][j]);
                    acc[i][j] = fmaf(a.z, b[j].z, acc[i][j]);
                    acc[i][j] = fmaf(a.w, b[j].w, acc[i][j]);
                }
            }
        }
        __syncthreads();
    }

    #pragma unroll
    for (int i = 0; i < 8; i++) {
        int node = node0 + 8 * ty + i;
        if (node < n) {
            float* o = g_y + (size_t)node * N_CLASSES + tx;
            o[0]  = acc[i][0];
            o[16] = acc[i][1];
            o[32] = acc[i][2];
            o[48] = acc[i][3];
        }
    }
}

// 5) scan apply (tops inlined): rowstart, fill cursor, dinv
__global__ void k_scan_apply(int n) {
    __shared__ int wsum[32];
    __shared__ int sexcl[SCAN_NB];
    const int lane = threadIdx.x & 31;
    const int wid  = threadIdx.x >> 5;

    if (wid == 0) {
        int i0 = 2 * lane, i1 = 2 * lane + 1;
        int a = (i0 < SCAN_NB) ? g_part[i0] : 0;
        int b = (i1 < SCAN_NB) ? g_part[i1] : 0;
        int pair = a + b, incl = pair;
        #pragma unroll
        for (int o = 1; o < 32; o <<= 1) {
            int tt = __shfl_up_sync(0xffffffffu, incl, o);
            if (lane >= o) incl += tt;
        }
        int excl = incl - pair;
        if (i0 < SCAN_NB) sexcl[i0] = excl;
        if (i1 < SCAN_NB) sexcl[i1] = excl + a;
    }
    __syncthreads();
    const int block_off = sexcl[blockIdx.x];

    int idx = blockIdx.x * SCAN_BLK + threadIdx.x;
    int v = (idx < n) ? g_cnt[idx] : 0;

    int incl = v;
    #pragma unroll
    for (int o = 1; o < 32; o <<= 1) {
        int t = __shfl_up_sync(0xffffffffu, incl, o);
        if (lane >= o) incl += t;
    }
    if (lane == 31) wsum[wid] = incl;
    __syncthreads();
    if (wid == 0) {
        int w = wsum[lane];
        int wi = w;
        #pragma unroll
        for (int o = 1; o < 32; o <<= 1) {
            int t = __shfl_up_sync(0xffffffffu, wi, o);
            if (lane >= o) wi += t;
        }
        wsum[lane] = wi - w;
    }
    __syncthreads();

    if (idx < n) {
        int excl = block_off + wsum[wid] + incl - v;
        g_rowstart[idx] = excl;
        g_fill[idx]     = excl;
        g_dinv[idx]     = rsqrtf((float)(v + 1));
    }
}

// 6) fill CSR columns, decoding raw buffer directly
__global__ void k_fill(const int* __restrict__ buf, int E, int N) {
    int e = blockIdx.x * blockDim.x + threadIdx.x;
    if (e >= E) return;
    int s, d;
    if (g_is64) { s = buf[2 * e];  d = buf[2 * E + 2 * e]; }
    else        { s = buf[e];      d = buf[E + e]; }
    if ((unsigned)s >= (unsigned)N) s = 0;
    if ((unsigned)d >= (unsigned)N) d = 0;
    int pos = atomicAdd(&g_fill[d], 1);
    g_col[pos] = s;
}

// ---------------------------------------------------------------------------
// Hop core: warp per node, lane owns one float2 (64 feats), unroll x8.
// ---------------------------------------------------------------------------
__device__ __forceinline__ float2 hop_accum(const float* __restrict__ yin,
                                            int i, int lane) {
    const float di = g_dinv[i];
    const int   rs = g_rowstart[i];
    const int   re = rs + g_cnt[i];

    float ax = 0.0f, ay = 0.0f;
    int e = rs;
    for (; e + 8 <= re; e += 8) {
        int   j[8];
        float w[8];
        float2 v[8];
        #pragma unroll
        for (int q = 0; q < 8; q++) j[q] = g_col[e + q];
        #pragma unroll
        for (int q = 0; q < 8; q++) w[q] = g_dinv[j[q]];
        #pragma unroll
        for (int q = 0; q < 8; q++)
            v[q] = reinterpret_cast<const float2*>(yin + (size_t)j[q] * N_CLASSES)[lane];
        #pragma unroll
        for (int q = 0; q < 8; q++) {
            ax = fmaf(w[q], v[q].x, ax);
            ay = fmaf(w[q], v[q].y, ay);
        }
    }
    for (; e < re; e++) {
        int jj = g_col[e];
        float w = g_dinv[jj];
        float2 v = reinterpret_cast<const float2*>(yin + (size_t)jj * N_CLASSES)[lane];
        ax = fmaf(w, v.x, ax); ay = fmaf(w, v.y, ay);
    }

    float2 self = reinterpret_cast<const float2*>(yin + (size_t)i * N_CLASSES)[lane];
    float2 o;
    o.x = fmaf(di, ax, di * di * self.x);
    o.y = fmaf(di, ay, di * di * self.y);
    return o;
}

// 7) hop 1: y -> h1
__global__ void k_hop1() {
    int warp = (blockIdx.x * blockDim.x + threadIdx.x) >> 5;
    int lane = threadIdx.x & 31;
    if (warp >= N_NODES) return;
    float2 o = hop_accum(g_y, warp, lane);
    reinterpret_cast<float2*>(g_h1 + (size_t)warp * N_CLASSES)[lane] = o;
}

// 8) hop 2 fused with bias + log_softmax
__global__ void k_hop2_head(const float* __restrict__ b, float* __restrict__ out) {
    int warp = (blockIdx.x * blockDim.x + threadIdx.x) >> 5;
    int lane = threadIdx.x & 31;
    if (warp >= N_NODES) return;

    float2 o  = hop_accum(g_h1, warp, lane);
    float2 bb = reinterpret_cast<const float2*>(b)[lane];
    o.x += bb.x;
    o.y += bb.y;

    float m = fmaxf(o.x, o.y);
    #pragma unroll
    for (int s = 16; s; s >>= 1) m = fmaxf(m, __shfl_xor_sync(0xffffffffu, m, s));

    float ssum = __expf(o.x - m) + __expf(o.y - m);
    #pragma unroll
    for (int s = 16; s; s >>= 1) ssum += __shfl_xor_sync(0xffffffffu, ssum, s);

    float ls = m + __logf(ssum);
    float2 r;
    r.x = o.x - ls;
    r.y = o.y - ls;
    reinterpret_cast<float2*>(out + (size_t)warp * N_CLASSES)[lane] = r;
}

// ---------------------------------------------------------------------------
// launch (8 kernels; k_lin 4th so ncu profiles it)
// ---------------------------------------------------------------------------
extern "C" void kernel_launch(void* const* d_in, const int* in_sizes, int n_in,
                              void* d_out, int out_size) {
    int ix = 0, ie = 1, iw = 2, ib = 3;
    for (int k = 0; k < n_in && k < 4; k++) {
        if      (in_sizes[k] == N_NODES * N_FEAT)   ix = k;
        else if (in_sizes[k] == 2 * N_EDGES)        ie = k;
        else if (in_sizes[k] == N_CLASSES * N_FEAT) iw = k;
        else if (in_sizes[k] == N_CLASSES)          ib = k;
    }
    const float* x    = (const float*)d_in[ix];
    const int*   ebuf = (const int*)d_in[ie];
    const float* W    = (const float*)d_in[iw];
    const float* b    = (const float*)d_in[ib];
    float* out = (float*)d_out;

    const int N = N_NODES;
    const int E = N_EDGES;

    static int smem_set = 0;
    if (!smem_set) {
        cudaFuncSetAttribute(k_lin, cudaFuncAttributeMaxDynamicSharedMemorySize, LIN_SMEM);
        smem_set = 1;
    }

    k_init         <<<(N + 255) / 256, 256>>>(ebuf, N);                 // 1
    k_count        <<<(E + 255) / 256, 256>>>(ebuf, E, N);              // 2
    k_scan_partials<<<SCAN_NB, SCAN_BLK>>>(N);                          // 3
    k_lin          <<<(N + LIN_TM - 1) / LIN_TM, 256, LIN_SMEM>>>(x, W, N); // 4 (profiled)
    k_scan_apply   <<<SCAN_NB, SCAN_BLK>>>(N);                          // 5
    k_fill         <<<(E + 255) / 256, 256>>>(ebuf, E, N);              // 6

    const long long hop_threads = (long long)N * 32;
    const int hop_blocks = (int)((hop_threads + 255) / 256);
    k_hop1     <<<hop_blocks, 256>>>();                                 // 7
    k_hop2_head<<<hop_blocks, 256>>>(b, out);                           // 8
}

// round 13
// speedup vs baseline: 8.5026x; 1.1643x over previous
#include <cuda_runtime.h>
#include <cstdint>

#define N_NODES   50000
#define N_EDGES   800000
#define N_FEAT    128
#define N_CLASSES 64

#define SCAN_BLK  1024
#define SCAN_NB   ((N_NODES + SCAN_BLK - 1) / SCAN_BLK)   // 49

#define LIN_TM    128                                     // nodes per k_lin block
#define LIN_KC    64                                      // k-chunk width
#define LIN_PADC  68                                      // padded chunk row (floats)
#define LIN_SMEM  ((LIN_TM + N_CLASSES) * LIN_PADC * 4)   // 52224 B dynamic smem

// -------- device scratch (no cudaMalloc allowed) --------
__device__ int   g_is64;
__device__ int   g_cnt[N_NODES];
__device__ int   g_fill[N_NODES];
__device__ int   g_rowstart[N_NODES];
__device__ float g_dinv[N_NODES];
__device__ int   g_col[N_EDGES];
__device__ int   g_part[SCAN_NB];
__device__ __align__(16) float g_y [(size_t)N_NODES * N_CLASSES];
__device__ __align__(16) float g_h1[(size_t)N_NODES * N_CLASSES];

// ---------------------------------------------------------------------------
// 1) init: zero counters; warp 0 of block 0 detects edge dtype via ballot.
// ---------------------------------------------------------------------------
__global__ void k_init(const int* __restrict__ ebuf, int n) {
    int i = blockIdx.x * blockDim.x + threadIdx.x;
    if (i < n) g_cnt[i] = 0;
    if (blockIdx.x == 0 && threadIdx.x < 32) {
        int nz = (ebuf[2 * threadIdx.x + 1] != 0) ? 1 : 0;
        unsigned ball = __ballot_sync(0xffffffffu, nz);
        if (threadIdx.x == 0) g_is64 = (ball == 0) ? 1 : 0;
    }
}

// 2) histogram of dst, decoding raw buffer directly
__global__ void k_count(const int* __restrict__ buf, int E, int N) {
    int e = blockIdx.x * blockDim.x + threadIdx.x;
    if (e >= E) return;
    int d = g_is64 ? buf[2 * E + 2 * e] : buf[E + e];
    if ((unsigned)d >= (unsigned)N) d = 0;
    atomicAdd(&g_cnt[d], 1);
}

// 3) per-block sums for the scan
__global__ void k_scan_partials(int n) {
    __shared__ int wsum[32];
    int idx  = blockIdx.x * SCAN_BLK + threadIdx.x;
    int lane = threadIdx.x & 31;
    int wid  = threadIdx.x >> 5;
    int v = (idx < n) ? g_cnt[idx] : 0;
    #pragma unroll
    for (int o = 16; o; o >>= 1) v += __shfl_xor_sync(0xffffffffu, v, o);
    if (lane == 0) wsum[wid] = v;
    __syncthreads();
    if (wid == 0) {
        int t = wsum[lane];
        #pragma unroll
        for (int o = 16; o; o >>= 1) t += __shfl_xor_sync(0xffffffffu, t, o);
        if (lane == 0) g_part[blockIdx.x] = t;
    }
}

// ---------------------------------------------------------------------------
// 4) y = x @ W^T — tiled GEMM (runs on side stream, overlapped with CSR build)
// ---------------------------------------------------------------------------
__global__ __launch_bounds__(256, 3)
void k_lin(const float* __restrict__ x, const float* __restrict__ W, int n) {
    extern __shared__ float sm[];
    float* ws = sm;                               // [N_CLASSES][LIN_PADC]
    float* xs = sm + N_CLASSES * LIN_PADC;        // [LIN_TM][LIN_PADC]

    const int t     = threadIdx.x;
    const int node0 = blockIdx.x * LIN_TM;
    const int tx    = t & 15;                     // classes tx + 16j
    const int ty    = t >> 4;                     // nodes 8*ty + i

    float acc[8][4] = {};

    #pragma unroll
    for (int c = 0; c < N_FEAT / LIN_KC; c++) {
        const int k0 = c * LIN_KC;

        for (int f = t; f < N_CLASSES * 16; f += 256) {
            int row = f >> 4, c4 = (f & 15) << 2;
            float4 v = reinterpret_cast<const float4*>(W + (size_t)row * N_FEAT + k0 + c4)[0];
            reinterpret_cast<float4*>(ws + row * LIN_PADC + c4)[0] = v;
        }
        for (int f = t; f < LIN_TM * 16; f += 256) {
            int row = f >> 4, c4 = (f & 15) << 2;
            int node = node0 + row;
            float4 v = (node < n)
                ? reinterpret_cast<const float4*>(x + (size_t)node * N_FEAT + k0 + c4)[0]
                : make_float4(0.f, 0.f, 0.f, 0.f);
            reinterpret_cast<float4*>(xs + row * LIN_PADC + c4)[0] = v;
        }
        __syncthreads();

        const float* xb = xs + (8 * ty) * LIN_PADC;
        #pragma unroll
        for (int k4 = 0; k4 < LIN_KC / 4; k4++) {
            float4 b[4];
            #pragma unroll
            for (int j = 0; j < 4; j++)
                b[j] = reinterpret_cast<const float4*>(ws + (tx + 16 * j) * LIN_PADC)[k4];
            #pragma unroll
            for (int i = 0; i < 8; i++) {
                float4 a = reinterpret_cast<const float4*>(xb + i * LIN_PADC)[k4];
                #pragma unroll
                for (int j = 0; j < 4; j++) {
                    acc[i][j] = fmaf(a.x, b[j].x, acc[i][j]);
                    acc[i][j] = fmaf(a.y, b[j].y, acc[i][j]);
                    acc[i][j] = fmaf(a.z, b[j].z, acc[i][j]);
                    acc[i][j] = fmaf(a.w, b[j].w, acc[i][j]);
                }
            }
        }
        __syncthreads();
    }

    #pragma unroll
    for (int i = 0; i < 8; i++) {
        int node = node0 + 8 * ty + i;
        if (node < n) {
            float* o = g_y + (size_t)node * N_CLASSES + tx;
            o[0]  = acc[i][0];
            o[16] = acc[i][1];
            o[32] = acc[i][2];
            o[48] = acc[i][3];
        }
    }
}

// 5) scan apply (tops inlined): rowstart, fill cursor, dinv
__global__ void k_scan_apply(int n) {
    __shared__ int wsum[32];
    __shared__ int sexcl[SCAN_NB];
    const int lane = threadIdx.x & 31;
    const int wid  = threadIdx.x >> 5;

    if (wid == 0) {
        int i0 = 2 * lane, i1 = 2 * lane + 1;
        int a = (i0 < SCAN_NB) ? g_part[i0] : 0;
        int b = (i1 < SCAN_NB) ? g_part[i1] : 0;
        int pair = a + b, incl = pair;
        #pragma unroll
        for (int o = 1; o < 32; o <<= 1) {
            int tt = __shfl_up_sync(0xffffffffu, incl, o);
            if (lane >= o) incl += tt;
        }
        int excl = incl - pair;
        if (i0 < SCAN_NB) sexcl[i0] = excl;
        if (i1 < SCAN_NB) sexcl[i1] = excl + a;
    }
    __syncthreads();
    const int block_off = sexcl[blockIdx.x];

    int idx = blockIdx.x * SCAN_BLK + threadIdx.x;
    int v = (idx < n) ? g_cnt[idx] : 0;

    int incl = v;
    #pragma unroll
    for (int o = 1; o < 32; o <<= 1) {
        int t = __shfl_up_sync(0xffffffffu, incl, o);
        if (lane >= o) incl += t;
    }
    if (lane == 31) wsum[wid] = incl;
    __syncthreads();
    if (wid == 0) {
        int w = wsum[lane];
        int wi = w;
        #pragma unroll
        for (int o = 1; o < 32; o <<= 1) {
            int t = __shfl_up_sync(0xffffffffu, wi, o);
            if (lane >= o) wi += t;
        }
        wsum[lane] = wi - w;
    }
    __syncthreads();

    if (idx < n) {
        int excl = block_off + wsum[wid] + incl - v;
        g_rowstart[idx] = excl;
        g_fill[idx]     = excl;
        g_dinv[idx]     = rsqrtf((float)(v + 1));
    }
}

// 6) fill CSR columns, decoding raw buffer directly
__global__ void k_fill(const int* __restrict__ buf, int E, int N) {
    int e = blockIdx.x * blockDim.x + threadIdx.x;
    if (e >= E) return;
    int s, d;
    if (g_is64) { s = buf[2 * e];  d = buf[2 * E + 2 * e]; }
    else        { s = buf[e];      d = buf[E + e]; }
    if ((unsigned)s >= (unsigned)N) s = 0;
    if ((unsigned)d >= (unsigned)N) d = 0;
    int pos = atomicAdd(&g_fill[d], 1);
    g_col[pos] = s;
}

// ---------------------------------------------------------------------------
// Hop core: warp per node, lane owns one float2 (64 feats), unroll x8.
// ---------------------------------------------------------------------------
__device__ __forceinline__ float2 hop_accum(const float* __restrict__ yin,
                                            int i, int lane) {
    const float di = g_dinv[i];
    const int   rs = g_rowstart[i];
    const int   re = rs + g_cnt[i];

    float ax = 0.0f, ay = 0.0f;
    int e = rs;
    for (; e + 8 <= re; e += 8) {
        int   j[8];
        float w[8];
        float2 v[8];
        #pragma unroll
        for (int q = 0; q < 8; q++) j[q] = g_col[e + q];
        #pragma unroll
        for (int q = 0; q < 8; q++) w[q] = g_dinv[j[q]];
        #pragma unroll
        for (int q = 0; q < 8; q++)
            v[q] = reinterpret_cast<const float2*>(yin + (size_t)j[q] * N_CLASSES)[lane];
        #pragma unroll
        for (int q = 0; q < 8; q++) {
            ax = fmaf(w[q], v[q].x, ax);
            ay = fmaf(w[q], v[q].y, ay);
        }
    }
    for (; e < re; e++) {
        int jj = g_col[e];
        float w = g_dinv[jj];
        float2 v = reinterpret_cast<const float2*>(yin + (size_t)jj * N_CLASSES)[lane];
        ax = fmaf(w, v.x, ax); ay = fmaf(w, v.y, ay);
    }

    float2 self = reinterpret_cast<const float2*>(yin + (size_t)i * N_CLASSES)[lane];
    float2 o;
    o.x = fmaf(di, ax, di * di * self.x);
    o.y = fmaf(di, ay, di * di * self.y);
    return o;
}

// 7) hop 1: y -> h1
__global__ void k_hop1() {
    int warp = (blockIdx.x * blockDim.x + threadIdx.x) >> 5;
    int lane = threadIdx.x & 31;
    if (warp >= N_NODES) return;
    float2 o = hop_accum(g_y, warp, lane);
    reinterpret_cast<float2*>(g_h1 + (size_t)warp * N_CLASSES)[lane] = o;
}

// 8) hop 2 fused with bias + log_softmax
__global__ void k_hop2_head(const float* __restrict__ b, float* __restrict__ out) {
    int warp = (blockIdx.x * blockDim.x + threadIdx.x) >> 5;
    int lane = threadIdx.x & 31;
    if (warp >= N_NODES) return;

    float2 o  = hop_accum(g_h1, warp, lane);
    float2 bb = reinterpret_cast<const float2*>(b)[lane];
    o.x += bb.x;
    o.y += bb.y;

    float m = fmaxf(o.x, o.y);
    #pragma unroll
    for (int s = 16; s; s >>= 1) m = fmaxf(m, __shfl_xor_sync(0xffffffffu, m, s));

    float ssum = __expf(o.x - m) + __expf(o.y - m);
    #pragma unroll
    for (int s = 16; s; s >>= 1) ssum += __shfl_xor_sync(0xffffffffu, ssum, s);

    float ls = m + __logf(ssum);
    float2 r;
    r.x = o.x - ls;
    r.y = o.y - ls;
    reinterpret_cast<float2*>(out + (size_t)warp * N_CLASSES)[lane] = r;
}

// ---------------------------------------------------------------------------
// launch: edge chain on capture stream; k_lin forked onto a side stream.
// Fork/join via events becomes graph edges under capture.
// ---------------------------------------------------------------------------
extern "C" void kernel_launch(void* const* d_in, const int* in_sizes, int n_in,
                              void* d_out, int out_size) {
    int ix = 0, ie = 1, iw = 2, ib = 3;
    for (int k = 0; k < n_in && k < 4; k++) {
        if      (in_sizes[k] == N_NODES * N_FEAT)   ix = k;
        else if (in_sizes[k] == 2 * N_EDGES)        ie = k;
        else if (in_sizes[k] == N_CLASSES * N_FEAT) iw = k;
        else if (in_sizes[k] == N_CLASSES)          ib = k;
    }
    const float* x    = (const float*)d_in[ix];
    const int*   ebuf = (const int*)d_in[ie];
    const float* W    = (const float*)d_in[iw];
    const float* b    = (const float*)d_in[ib];
    float* out = (float*)d_out;

    const int N = N_NODES;
    const int E = N_EDGES;

    static int inited = 0;
    static cudaStream_t s1;
    static cudaEvent_t ev_fork, ev_join;
    if (!inited) {
        cudaFuncSetAttribute(k_lin, cudaFuncAttributeMaxDynamicSharedMemorySize, LIN_SMEM);
        cudaStreamCreateWithFlags(&s1, cudaStreamNonBlocking);
        cudaEventCreateWithFlags(&ev_fork, cudaEventDisableTiming);
        cudaEventCreateWithFlags(&ev_join, cudaEventDisableTiming);
        inited = 1;
    }

    // fork: side stream runs the GEMM concurrently with the CSR build
    cudaEventRecord(ev_fork, 0);
    cudaStreamWaitEvent(s1, ev_fork, 0);
    k_lin<<<(N + LIN_TM - 1) / LIN_TM, 256, LIN_SMEM, s1>>>(x, W, N);
    cudaEventRecord(ev_join, s1);

    // edge chain on the capture stream
    k_init         <<<(N + 255) / 256, 256>>>(ebuf, N);
    k_count        <<<(E + 255) / 256, 256>>>(ebuf, E, N);
    k_scan_partials<<<SCAN_NB, SCAN_BLK>>>(N);
    k_scan_apply   <<<SCAN_NB, SCAN_BLK>>>(N);
    k_fill         <<<(E + 255) / 256, 256>>>(ebuf, E, N);

    // join: hops need both the CSR and y
    cudaStreamWaitEvent(0, ev_join, 0);

    const long long hop_threads = (long long)N * 32;
    const int hop_blocks = (int)((hop_threads + 255) / 256);
    k_hop1     <<<hop_blocks, 256>>>();
    k_hop2_head<<<hop_blocks, 256>>>(b, out);
}